// round 15
// baseline (speedup 1.0000x reference)
#include <cuda_runtime.h>

#define MESH   4194304
#define BLOCK  256
#define GRID   740                 // 5 * 148 SMs; blocks 0..395 take 6 tiles, rest 5
#define TILE   1024                // elements per tile (4 contiguous per thread)
#define NTILES (MESH / TILE)       // 4096
#define NSTAGE 3
#define THPAD  4                   // s_th[stage][THPAD-1] holds theta[base-1]

#define INV0F 1.5707963            // expansion point for 1/avg_len (= pi/2)
#define K2EXP (-2.26618007f)       // -(pi/2)*log2(e): exp(-v*pi/2) = 2^(v*K2EXP)

// Accumulators (self-reset by finalizer for graph replay).
__device__ double   g_loss_v = 0.0;
__device__ double   g_loss_s = 0.0;
__device__ double   g_S0     = 0.0;
__device__ double   g_S1     = 0.0;
__device__ float    g_last_t = 0.0f;   // o^2 of last edge (== 1 - dots[M-1]^2)
__device__ float    g_thm2   = 0.0f;   // |theta[MESH-2]|
__device__ unsigned g_done   = 0u;

__device__ __forceinline__ unsigned smem_u32(const void* p) {
    unsigned a;
    asm("{ .reg .u64 t; cvta.to.shared.u64 t, %1; cvt.u32.u64 %0, t; }"
        : "=r"(a) : "l"(p));
    return a;
}
__device__ __forceinline__ void cp16(unsigned d, const void* s) {   // L1-bypass
    asm volatile("cp.async.cg.shared.global [%0], [%1], 16;" :: "r"(d), "l"(s));
}
__device__ __forceinline__ void cp8(unsigned d, const void* s) {
    asm volatile("cp.async.ca.shared.global [%0], [%1], 8;" :: "r"(d), "l"(s));
}
__device__ __forceinline__ void cp4(unsigned d, const void* s) {
    asm volatile("cp.async.ca.shared.global [%0], [%1], 4;" :: "r"(d), "l"(s));
}
#define CP_COMMIT() asm volatile("cp.async.commit_group;" ::: "memory")
#define CP_WAIT1()  asm volatile("cp.async.wait_group 1;"  ::: "memory")

__device__ __forceinline__ float ex2_ap(float x) {
    float r; asm("ex2.approx.f32 %0, %1;" : "=f"(r) : "f"(x)); return r;
}

__global__ void __launch_bounds__(BLOCK, 5)
k_fused(const float*  __restrict__ theta,
        const float2* __restrict__ state2,
        const float4* __restrict__ state4,
        float* __restrict__ out) {
    __shared__ __align__(16) float2 s_st[NSTAGE][TILE + 2];
    __shared__ __align__(16) float  s_th[NSTAGE][TILE + THPAD];

    const int tid = threadIdx.x;
    const int bid = blockIdx.x;
    const int mycount = (NTILES - bid + GRID - 1) / GRID;   // 6 or 5

    // ---- async copy of tile (bid + i*GRID) into stage s ----
    auto copy_tile = [&](int i, int s) {
        const int t    = bid + i * GRID;
        const int base = t * TILE;
        // states: TILE float2 = 512 x 16B -> 2 cp16 per thread
        cp16(smem_u32(&s_st[s][tid * 2]),       state4 + (base >> 1) + tid);
        cp16(smem_u32(&s_st[s][512 + tid * 2]), state4 + (base >> 1) + 256 + tid);
        // thetas: TILE floats = 256 x 16B -> 1 cp16 per thread
        if (t != NTILES - 1 || tid != 255) {
            cp16(smem_u32(&s_th[s][THPAD + tid * 4]), theta + base + tid * 4);
        } else {     // final tile: theta has MESH-1 elems; virtual theta[M-1]=0
            cp8(smem_u32(&s_th[s][THPAD + 1020]), theta + base + 1020);
            cp4(smem_u32(&s_th[s][THPAD + 1022]), theta + base + 1022);
            s_th[s][THPAD + 1023] = 0.0f;
        }
        if (tid == 0) {
            // state halo u[base+TILE] (wrap -> state[0] == deformed[0])
            const float2* src = (t + 1 < NTILES) ? (state2 + base + TILE) : state2;
            cp8(smem_u32(&s_st[s][TILE]), src);
            // theta halo theta[base-1] (virtual 0 at t==0)
            if (t > 0) cp4(smem_u32(&s_th[s][THPAD - 1]), theta + base - 1);
            else       s_th[s][THPAD - 1] = 0.0f;
        }
    };

    float sum_v = 0.0f, sum_s = 0.0f, S0 = 0.0f, S1 = 0.0f;

    // ---- compute tile i (stage s): 4 contiguous edges per thread ----
    auto compute = [&](int i, int s) {
        const int t = bid + i * GRID;
        const int e = tid * 4;                        // local element base

        const float4 u01  = *reinterpret_cast<const float4*>(&s_st[s][e]);
        const float4 u23  = *reinterpret_cast<const float4*>(&s_st[s][e + 2]);
        const float2 u4   = s_st[s][e + 4];           // halo at e=1020 -> s_st[1024]
        const float  thm1 = s_th[s][THPAD + e - 1];
        const float4 th   = *reinterpret_cast<const float4*>(&s_th[s][THPAD + e]);

        // Edge j: dt = theta[j]-theta[j-1]; unit states + sin^2+cos^2=1
        // => vols = |o|, o = sin(dt)*dd - cos(dt)*cr  (no sqrt).
        float dt0 = th.x - thm1;
        float dt1 = th.y - th.x;
        float dt2 = th.z - th.y;
        float dt3 = th.w - th.z;

        float dd0 = fmaf(u01.x, u01.z,  u01.y * u01.w);
        float cr0 = fmaf(u01.y, u01.z, -u01.x * u01.w);
        float dd1 = fmaf(u01.z, u23.x,  u01.w * u23.y);
        float cr1 = fmaf(u01.w, u23.x, -u01.z * u23.y);
        float dd2 = fmaf(u23.x, u23.z,  u23.y * u23.w);
        float cr2 = fmaf(u23.y, u23.z, -u23.x * u23.w);
        float dd3 = fmaf(u23.z, u4.x,   u23.w * u4.y);
        float cr3 = fmaf(u23.w, u4.x,  -u23.z * u4.y);

        float a0 = dt0 * dt0, a1 = dt1 * dt1, a2 = dt2 * dt2, a3 = dt3 * dt3;
        float s0 = dt0 * fmaf(a0, -0.16666667f, 1.0f);             // sin err<1e-8
        float s1 = dt1 * fmaf(a1, -0.16666667f, 1.0f);
        float s2 = dt2 * fmaf(a2, -0.16666667f, 1.0f);
        float s3 = dt3 * fmaf(a3, -0.16666667f, 1.0f);
        float c0 = fmaf(a0, fmaf(a0, 4.1666667e-2f, -0.5f), 1.0f); // cos err<1e-9
        float c1 = fmaf(a1, fmaf(a1, 4.1666667e-2f, -0.5f), 1.0f);
        float c2 = fmaf(a2, fmaf(a2, 4.1666667e-2f, -0.5f), 1.0f);
        float c3 = fmaf(a3, fmaf(a3, 4.1666667e-2f, -0.5f), 1.0f);

        float o0 = fmaf(s0, dd0, -c0 * cr0);
        float o1 = fmaf(s1, dd1, -c1 * cr1);
        float o2 = fmaf(s2, dd2, -c2 * cr2);
        float o3 = fmaf(s3, dd3, -c3 * cr3);
        float v0 = fabsf(o0), v1 = fabsf(o1), v2 = fabsf(o2), v3 = fabsf(o3);

        sum_v += (v0 + v1) + (v2 + v3);
        sum_s  = fmaf(o0, o0, fmaf(o1, o1, fmaf(o2, o2, fmaf(o3, o3, sum_s))));

        float w0 = fabsf(dt0), w1 = fabsf(dt1), w2 = fabsf(dt2), w3 = fabsf(dt3);
        if (t == NTILES - 1 && tid == BLOCK - 1) {
            g_thm2   = w3;          // |theta[MESH-2]| (theta[M-1] virtual 0)
            g_last_t = o3 * o3;     // exp arg of sim_last
            w3 = 0.0f;              // last edge excluded from S0/S1
        }

        float e0 = ex2_ap(v0 * K2EXP), e1 = ex2_ap(v1 * K2EXP);
        float e2 = ex2_ap(v2 * K2EXP), e3 = ex2_ap(v3 * K2EXP);
        float we0 = w0 * e0, we1 = w1 * e1, we2 = w2 * e2, we3 = w3 * e3;
        S0 += (we0 + we1) + (we2 + we3);
        S1  = fmaf(we0, v0, fmaf(we1, v1, fmaf(we2, v2, fmaf(we3, v3, S1))));
    };

    // ---- static 3-stage cp.async pipeline, ONE barrier per tile ----
    copy_tile(0, 0);
    CP_COMMIT();
    if (mycount > 1) copy_tile(1, 1);
    CP_COMMIT();
    int s = 0, s2 = 2;                   // stage of tile i, stage of tile i+2
    for (int i = 0; i < mycount; ++i) {
        CP_WAIT1();                  // my copies for tile i complete
        __syncthreads();             // tile i visible; orders compute(i-1)
                                     // before copy(i+2) overwrites its stage
        compute(i, s);
        if (i + 2 < mycount) copy_tile(i + 2, s2);
        CP_COMMIT();
        s  = (s  + 1 == NSTAGE) ? 0 : s  + 1;
        s2 = (s2 + 1 == NSTAGE) ? 0 : s2 + 1;
    }

    // ---- Block reduction: 4 sums -> 4 double atomics per block ----
    const int lane = tid & 31;
    #pragma unroll
    for (int o = 16; o > 0; o >>= 1) {
        sum_v += __shfl_down_sync(0xFFFFFFFFu, sum_v, o);
        sum_s += __shfl_down_sync(0xFFFFFFFFu, sum_s, o);
        S0    += __shfl_down_sync(0xFFFFFFFFu, S0, o);
        S1    += __shfl_down_sync(0xFFFFFFFFu, S1, o);
    }
    __shared__ float red[4][BLOCK / 32];
    const int w = tid >> 5;
    if (lane == 0) { red[0][w] = sum_v; red[1][w] = sum_s; red[2][w] = S0; red[3][w] = S1; }
    __syncthreads();
    if (tid == 0) {
        double rv = 0, rs = 0, r0 = 0, r1 = 0;
        #pragma unroll
        for (int i = 0; i < BLOCK / 32; i++) {
            rv += (double)red[0][i]; rs += (double)red[1][i];
            r0 += (double)red[2][i]; r1 += (double)red[3][i];
        }
        atomicAdd(&g_loss_v, rv);
        atomicAdd(&g_loss_s, rs);
        atomicAdd(&g_S0, r0);
        atomicAdd(&g_S1, r1);

        // ---- Last block out: finalize + self-reset (graph-replayable) ----
        __threadfence();
        unsigned p = atomicAdd(&g_done, 1u);
        if (p == (unsigned)GRID - 1u) {
            double lv = atomicAdd(&g_loss_v, 0.0);
            double ls = atomicAdd(&g_loss_s, 0.0);
            double T0 = atomicAdd(&g_S0, 0.0);
            double T1 = atomicAdd(&g_S1, 0.0);
            double inv = (double)MESH / fabs(lv);   // exact 1/avg_len
            double dlt = inv - INV0F;               // tiny (~1e-3)
            double so2 = T0 - T1 * dlt
                       + (double)g_thm2 * exp(-(double)g_last_t * inv);
            out[0] = (float)(lv + ls + so2);
            g_loss_v = 0.0; g_loss_s = 0.0;
            g_S0 = 0.0; g_S1 = 0.0;
            g_done = 0u;
            __threadfence();
        }
    }
}

extern "C" void kernel_launch(void* const* d_in, const int* in_sizes, int n_in,
                              void* d_out, int out_size) {
    const float* theta = (const float*)d_in[0];
    const float* state = (const float*)d_in[1];
    float* out = (float*)d_out;

    k_fused<<<GRID, BLOCK>>>(theta, (const float2*)state,
                             (const float4*)state, out);
}

// round 16
// speedup vs baseline: 1.0225x; 1.0225x over previous
#include <cuda_runtime.h>

#define MESH   4194304
#define BLOCK  256
#define GRID   740                 // 5 * 148 SMs
#define TILE   1024                // elements per tile (4 contiguous per thread)
#define NTILES (MESH / TILE)       // 4096
#define NSTAGE 3
#define THPAD  4                   // s_th[stage][THPAD-1] holds theta[base-1]

#define INV0F 1.5707963            // expansion point for 1/avg_len (= pi/2)
#define K2EXP (-2.26618007f)       // -(pi/2)*log2(e): exp(-v*pi/2) = 2^(v*K2EXP)

// Accumulators (self-reset by finalizer for graph replay).
__device__ double   g_loss_v = 0.0;
__device__ double   g_loss_s = 0.0;
__device__ double   g_S0     = 0.0;
__device__ double   g_S1     = 0.0;
__device__ float    g_last_t = 0.0f;   // o^2 of last edge (== 1 - dots[M-1]^2)
__device__ float    g_thm2   = 0.0f;   // |theta[MESH-2]|
__device__ unsigned g_done   = 0u;

__device__ __forceinline__ unsigned smem_u32(const void* p) {
    unsigned a;
    asm("{ .reg .u64 t; cvta.to.shared.u64 t, %1; cvt.u32.u64 %0, t; }"
        : "=r"(a) : "l"(p));
    return a;
}
__device__ __forceinline__ void mbar_init(unsigned m, unsigned cnt) {
    asm volatile("mbarrier.init.shared.b64 [%0], %1;" :: "r"(m), "r"(cnt) : "memory");
}
__device__ __forceinline__ void mbar_expect_tx(unsigned m, unsigned bytes) {
    asm volatile("mbarrier.arrive.expect_tx.shared.b64 _, [%0], %1;"
                 :: "r"(m), "r"(bytes) : "memory");
}
__device__ __forceinline__ void bulk_g2s(unsigned dst, const void* src,
                                         unsigned bytes, unsigned m) {
    asm volatile("cp.async.bulk.shared::cta.global.mbarrier::complete_tx::bytes "
                 "[%0], [%1], %2, [%3];"
                 :: "r"(dst), "l"(src), "r"(bytes), "r"(m) : "memory");
}
__device__ __forceinline__ void mbar_wait(unsigned m, unsigned parity) {
    asm volatile(
        "{\n\t.reg .pred P;\n\t"
        "WL_%=:\n\t"
        "mbarrier.try_wait.parity.acquire.cta.shared::cta.b64 P, [%0], %1, 0x989680;\n\t"
        "@P bra.uni WD_%=;\n\t"
        "bra.uni WL_%=;\n\t"
        "WD_%=:\n\t}"
        :: "r"(m), "r"(parity) : "memory");
}
__device__ __forceinline__ float ex2_ap(float x) {
    float r; asm("ex2.approx.f32 %0, %1;" : "=f"(r) : "f"(x)); return r;
}

__global__ void __launch_bounds__(BLOCK, 5)
k_fused(const float*  __restrict__ theta,
        const float2* __restrict__ state2,
        float* __restrict__ out) {
    __shared__ __align__(16) float2 s_st[NSTAGE][TILE + 2];       // 8208 B/stage
    __shared__ __align__(16) float  s_th[NSTAGE][THPAD + TILE];   // 4112 B/stage
    __shared__ __align__(8)  unsigned long long s_mbar[NSTAGE];

    const int tid = threadIdx.x;
    const int bid = blockIdx.x;
    const int mycount = (NTILES - bid + GRID - 1) / GRID;   // 6 or 5

    // ---- tid0: issue TMA bulk copies for tile (bid + i*GRID) into stage s ----
    auto issue_copy = [&](int i, int s) {
        const int t    = bid + i * GRID;
        const int base = t * TILE;
        const unsigned mb = smem_u32(&s_mbar[s]);
        unsigned st_bytes, th_bytes;
        const float* th_src;
        unsigned th_dst = smem_u32(&s_th[s][0]);

        if (t + 1 < NTILES) {
            st_bytes = (TILE + 2) * 8;            // 8208: includes halo (+1 junk)
        } else {
            st_bytes = TILE * 8;                  // 8192: halo = state[0] (wrap)
            s_st[s][TILE] = state2[0];            // generic store, disjoint bytes
        }
        if (t == 0) {
            th_bytes = TILE * 4;                  // 4096: theta[0..1024)
            th_src   = theta;
            th_dst  += THPAD * 4;
            s_th[s][THPAD - 1] = 0.0f;            // virtual theta[-1] = 0
        } else if (t + 1 < NTILES) {
            th_bytes = (THPAD + TILE) * 4;        // 4112: theta[base-4..base+1024)
            th_src   = theta + base - THPAD;
        } else {                                  // last: theta has MESH-1 elems
            th_bytes = (THPAD + TILE - 4) * 4;    // 4096: theta[base-4..base+1020)
            th_src   = theta + base - THPAD;
            s_th[s][THPAD + 1020] = theta[base + 1020];
            s_th[s][THPAD + 1021] = theta[base + 1021];
            s_th[s][THPAD + 1022] = theta[base + 1022];
            s_th[s][THPAD + 1023] = 0.0f;         // virtual theta[M-1] = 0
        }
        mbar_expect_tx(mb, st_bytes + th_bytes);
        bulk_g2s(smem_u32(&s_st[s][0]), state2 + base, st_bytes, mb);
        bulk_g2s(th_dst, th_src, th_bytes, mb);
    };

    float sum_v = 0.0f, sum_s = 0.0f, S0 = 0.0f, S1 = 0.0f;

    // ---- compute tile i (stage s): 4 contiguous edges per thread ----
    auto compute = [&](int i, int s) {
        const int t = bid + i * GRID;
        const int e = tid * 4;                        // local element base

        const float4 u01  = *reinterpret_cast<const float4*>(&s_st[s][e]);
        const float4 u23  = *reinterpret_cast<const float4*>(&s_st[s][e + 2]);
        const float2 u4   = s_st[s][e + 4];
        const float  thm1 = s_th[s][THPAD + e - 1];
        const float4 th   = *reinterpret_cast<const float4*>(&s_th[s][THPAD + e]);

        // Edge j: dt = theta[j]-theta[j-1]; unit states + sin^2+cos^2=1
        // => vols = |o|, o = sin(dt)*dd - cos(dt)*cr  (no sqrt).
        float dt0 = th.x - thm1;
        float dt1 = th.y - th.x;
        float dt2 = th.z - th.y;
        float dt3 = th.w - th.z;

        float dd0 = fmaf(u01.x, u01.z,  u01.y * u01.w);
        float cr0 = fmaf(u01.y, u01.z, -u01.x * u01.w);
        float dd1 = fmaf(u01.z, u23.x,  u01.w * u23.y);
        float cr1 = fmaf(u01.w, u23.x, -u01.z * u23.y);
        float dd2 = fmaf(u23.x, u23.z,  u23.y * u23.w);
        float cr2 = fmaf(u23.y, u23.z, -u23.x * u23.w);
        float dd3 = fmaf(u23.z, u4.x,   u23.w * u4.y);
        float cr3 = fmaf(u23.w, u4.x,  -u23.z * u4.y);

        float a0 = dt0 * dt0, a1 = dt1 * dt1, a2 = dt2 * dt2, a3 = dt3 * dt3;
        float s0 = dt0 * fmaf(a0, -0.16666667f, 1.0f);             // sin err<1e-8
        float s1 = dt1 * fmaf(a1, -0.16666667f, 1.0f);
        float s2 = dt2 * fmaf(a2, -0.16666667f, 1.0f);
        float s3 = dt3 * fmaf(a3, -0.16666667f, 1.0f);
        float c0 = fmaf(a0, fmaf(a0, 4.1666667e-2f, -0.5f), 1.0f); // cos err<1e-9
        float c1 = fmaf(a1, fmaf(a1, 4.1666667e-2f, -0.5f), 1.0f);
        float c2 = fmaf(a2, fmaf(a2, 4.1666667e-2f, -0.5f), 1.0f);
        float c3 = fmaf(a3, fmaf(a3, 4.1666667e-2f, -0.5f), 1.0f);

        float o0 = fmaf(s0, dd0, -c0 * cr0);
        float o1 = fmaf(s1, dd1, -c1 * cr1);
        float o2 = fmaf(s2, dd2, -c2 * cr2);
        float o3 = fmaf(s3, dd3, -c3 * cr3);
        float v0 = fabsf(o0), v1 = fabsf(o1), v2 = fabsf(o2), v3 = fabsf(o3);

        sum_v += (v0 + v1) + (v2 + v3);
        sum_s  = fmaf(o0, o0, fmaf(o1, o1, fmaf(o2, o2, fmaf(o3, o3, sum_s))));

        float w0 = fabsf(dt0), w1 = fabsf(dt1), w2 = fabsf(dt2), w3 = fabsf(dt3);
        if (t == NTILES - 1 && tid == BLOCK - 1) {
            g_thm2   = w3;          // |theta[MESH-2]| (theta[M-1] virtual 0)
            g_last_t = o3 * o3;     // exp arg of sim_last
            w3 = 0.0f;              // last edge excluded from S0/S1
        }

        float e0 = ex2_ap(v0 * K2EXP), e1 = ex2_ap(v1 * K2EXP);
        float e2 = ex2_ap(v2 * K2EXP), e3 = ex2_ap(v3 * K2EXP);
        float we0 = w0 * e0, we1 = w1 * e1, we2 = w2 * e2, we3 = w3 * e3;
        S0 += (we0 + we1) + (we2 + we3);
        S1  = fmaf(we0, v0, fmaf(we1, v1, fmaf(we2, v2, fmaf(we3, v3, S1))));
    };

    // ---- TMA-bulk 3-stage pipeline, ONE barrier per tile ----
    if (tid == 0) {
        #pragma unroll
        for (int s = 0; s < NSTAGE; ++s) mbar_init(smem_u32(&s_mbar[s]), 1);
        asm volatile("fence.proxy.async.shared::cta;" ::: "memory");
    }
    __syncthreads();                 // mbarriers initialized before any TMA
    if (tid == 0) {
        issue_copy(0, 0);
        if (mycount > 1) issue_copy(1, 1);
    }

    int s = 0, s2 = 2;               // stage of tile i, stage of tile i+2
    for (int i = 0; i < mycount; ++i) {
        mbar_wait(smem_u32(&s_mbar[s]), (unsigned)((i / NSTAGE) & 1));
        __syncthreads();             // tile i visible (incl. tid0 generic stores);
                                     // orders compute(i-1) before stage-s2 reuse
        compute(i, s);
        if (tid == 0 && i + 2 < mycount) issue_copy(i + 2, s2);
        s  = (s  + 1 == NSTAGE) ? 0 : s  + 1;
        s2 = (s2 + 1 == NSTAGE) ? 0 : s2 + 1;
    }

    // ---- Block reduction: 4 sums -> 4 double atomics per block ----
    const int lane = tid & 31;
    #pragma unroll
    for (int o = 16; o > 0; o >>= 1) {
        sum_v += __shfl_down_sync(0xFFFFFFFFu, sum_v, o);
        sum_s += __shfl_down_sync(0xFFFFFFFFu, sum_s, o);
        S0    += __shfl_down_sync(0xFFFFFFFFu, S0, o);
        S1    += __shfl_down_sync(0xFFFFFFFFu, S1, o);
    }
    __shared__ float red[4][BLOCK / 32];
    const int w = tid >> 5;
    if (lane == 0) { red[0][w] = sum_v; red[1][w] = sum_s; red[2][w] = S0; red[3][w] = S1; }
    __syncthreads();
    if (tid == 0) {
        double rv = 0, rs = 0, r0 = 0, r1 = 0;
        #pragma unroll
        for (int i = 0; i < BLOCK / 32; i++) {
            rv += (double)red[0][i]; rs += (double)red[1][i];
            r0 += (double)red[2][i]; r1 += (double)red[3][i];
        }
        atomicAdd(&g_loss_v, rv);
        atomicAdd(&g_loss_s, rs);
        atomicAdd(&g_S0, r0);
        atomicAdd(&g_S1, r1);

        // ---- Last block out: finalize + self-reset (graph-replayable) ----
        __threadfence();
        unsigned p = atomicAdd(&g_done, 1u);
        if (p == (unsigned)GRID - 1u) {
            double lv = atomicAdd(&g_loss_v, 0.0);
            double ls = atomicAdd(&g_loss_s, 0.0);
            double T0 = atomicAdd(&g_S0, 0.0);
            double T1 = atomicAdd(&g_S1, 0.0);
            double inv = (double)MESH / fabs(lv);   // exact 1/avg_len
            double dlt = inv - INV0F;               // tiny (~1e-3)
            double so2 = T0 - T1 * dlt
                       + (double)g_thm2 * exp(-(double)g_last_t * inv);
            out[0] = (float)(lv + ls + so2);
            g_loss_v = 0.0; g_loss_s = 0.0;
            g_S0 = 0.0; g_S1 = 0.0;
            g_done = 0u;
            __threadfence();
        }
    }
}

extern "C" void kernel_launch(void* const* d_in, const int* in_sizes, int n_in,
                              void* d_out, int out_size) {
    const float* theta = (const float*)d_in[0];
    const float* state = (const float*)d_in[1];
    float* out = (float*)d_out;

    k_fused<<<GRID, BLOCK>>>(theta, (const float2*)state, out);
}